// round 16
// baseline (speedup 1.0000x reference)
#include <cuda_runtime.h>
#include <cuda_fp16.h>
#include <mma.h>
#include <cstdint>

using namespace nvcuda;

// ---------------------------------------------------------------------------
#define N_ROWS 32768     // b*h*w = 8*64*64
#define C_DIM  256
#define K_CODES 2048
#define CD     260       // c+4
#define H1W    320       // padded hidden1 / wn width

// Scratch (device globals -- allocation is forbidden)
__device__ __half  g_x16[N_ROWS * C_DIM];                 // fp16 x_flat (n,256)
__device__ float   g_norm2[N_ROWS];                       // sum x^2 per row (fp32)
__device__ __half  g_mn16[K_CODES * C_DIM];               // normalized codebook fp16
__device__ __half  g_score[(size_t)N_ROWS * K_CODES];     // score, then p (in place)
__device__ float   g_sums[K_CODES * CD];
__device__ float   g_counts[K_CODES];
__device__ __half  g_wn[K_CODES * H1W];                   // l2norm(new_w) row-major
__device__ __half  g_wnT[H1W * K_CODES];                  // transposed [320][2048]
__device__ __half  g_h1[(size_t)N_ROWS * H1W];            // p @ wn  (n,320)
__device__ __half  g_h2[(size_t)N_ROWS * C_DIM];          // gelu(h1@w1+b1)
__device__ __half  g_w1T[C_DIM * H1W];                    // w1^T fp16 [256][320] pad
__device__ __half  g_w2T[C_DIM * C_DIM];                  // w2^T fp16

// ---------------------------------------------------------------------------
#define CP_ASYNC16(dst, src) \
    asm volatile("cp.async.cg.shared.global [%0], [%1], 16;\n" \
                 :: "r"(dst), "l"(src) : "memory")
#define CP_COMMIT asm volatile("cp.async.commit_group;\n" ::: "memory")
#define CP_WAIT1  asm volatile("cp.async.wait_group 1;\n" ::: "memory")
#define CP_WAIT0  asm volatile("cp.async.wait_group 0;\n" ::: "memory")

__device__ __forceinline__ uint32_t smem_u32(const void* p) {
    uint32_t a;
    asm("{ .reg .u64 t; cvta.to.shared.u64 t, %1; cvt.u32.u64 %0, t; }"
        : "=r"(a) : "l"(p));
    return a;
}

__device__ __forceinline__ float gelu_tanh(float v) {
    float u = 0.7978845608028654f * (v + 0.044715f * v * v * v);
    return 0.5f * v * (1.0f + tanhf(u));
}

// ---------------------------------------------------------------------------
// prep: zero sums/counts/norm2, build transposed fp16 weights
__global__ void prep_misc_kernel(const float* __restrict__ w1,
                                 const float* __restrict__ w2) {
    int t = blockIdx.x * blockDim.x + threadIdx.x;
    int nthr = gridDim.x * blockDim.x;
    for (int i = t; i < K_CODES * CD; i += nthr) g_sums[i] = 0.f;
    for (int i = t; i < K_CODES; i += nthr) g_counts[i] = 0.f;
    for (int i = t; i < N_ROWS; i += nthr) g_norm2[i] = 0.f;
    for (int i = t; i < C_DIM * H1W; i += nthr) {
        int j = i / H1W, k = i % H1W;
        g_w1T[i] = __float2half(k < CD ? w1[k * C_DIM + j] : 0.f);
    }
    for (int i = t; i < C_DIM * C_DIM; i += nthr) {
        int j = i >> 8, k = i & 255;
        g_w2T[i] = __float2half(w2[k * C_DIM + j]);
    }
}

// NCHW -> (n,256) fp16 transpose + partial row-norm2 atomics.
// grid (128, 8, 8), block (32, 8)
__global__ void prep_x_kernel(const float* __restrict__ x) {
    __shared__ float tile[32][33];
    int b = blockIdx.z, c0 = blockIdx.y * 32, s0 = blockIdx.x * 32;
    int tx = threadIdx.x, ty = threadIdx.y;
#pragma unroll
    for (int j = 0; j < 32; j += 8)
        tile[ty + j][tx] = x[(size_t)(b * 256 + c0 + ty + j) * 4096 + s0 + tx];
    __syncthreads();
#pragma unroll
    for (int j = 0; j < 32; j += 8) {
        int c = c0 + tx, s = s0 + ty + j, r = (b << 12) + s;
        float v = tile[tx][ty + j];
        g_x16[r * C_DIM + c] = __float2half(v);
        float sq = v * v;
#pragma unroll
        for (int o = 16; o; o >>= 1) sq += __shfl_xor_sync(0xffffffffu, sq, o);
        if (tx == 0) atomicAdd(&g_norm2[r], sq);
    }
}

// normalize codebook feature rows -> g_mn16. warp per row.
__global__ void prep_mn_kernel(const float* __restrict__ fw) {
    int wid = threadIdx.x >> 5, lane = threadIdx.x & 31;
    int k = blockIdx.x * 8 + wid;
    if (k >= K_CODES) return;
    const float* p = fw + (size_t)k * CD;
    float v[8], s = 0.f;
#pragma unroll
    for (int j = 0; j < 8; j++) { v[j] = p[lane + j * 32]; s += v[j] * v[j]; }
#pragma unroll
    for (int o = 16; o; o >>= 1) s += __shfl_xor_sync(0xffffffffu, s, o);
    float ri = 1.0f / fmaxf(sqrtf(s), 1e-12f);
#pragma unroll
    for (int j = 0; j < 8; j++)
        g_mn16[k * C_DIM + lane + j * 32] = __float2half(v[j] * ri);
}

// ---------------------------------------------------------------------------
// Streaming HMMA GEMM: CTA tile 128 x NT, 128 threads, 4 warps (2x2),
// WARP TILE 64 x NT/2 (fragment-load:MMA ratio 0.5 vs 0.75 -> smem reads
// -33%; kernel was smem-crossbar bound at L1=58.5%). BK=64, cp.async
// 3-stage ring, prefetch distance 2, one barrier per iter AFTER the wait.
// __launch_bounds__(128,2): 256 regs/thread available, 2 CTAs/SM.
// MODE 1: score = x16 @ mn^T  (*rinv)   -> g_score fp16   (NT=128, grid.y=16)
// MODE 2: h1    = p @ wnT^T             -> g_h1 fp16      (NT=128/64 split)
// MODE 3: h2    = gelu(h1 @ w1T^T + b1) -> g_h2 fp16      (NT=128, grid.y=2)
// MODE 4: out   = h2 @ w2T^T + b2       -> NCHW fp32      (NT=128, grid.y=2)
template <int MODE, int NT, int N0OFF>
__global__ __launch_bounds__(128, 2) void st_gemm(const float* __restrict__ bias,
                                                  float* __restrict__ out4) {
    constexpr int K  = (MODE == 1) ? 256 : (MODE == 2) ? 2048 : (MODE == 3) ? 320 : 256;
    constexpr int NIT = K / 64;
    constexpr int SA = 72;                       // smem k-stride (halves)
    constexpr int ASZ = 128 * SA;                // halves per A stage
    constexpr int BSZ = NT * SA;
    constexpr int STG = ASZ + BSZ;
    constexpr int WNT = NT / 2;                  // per-warp N (warp grid 2x2)
    constexpr int NF  = WNT / 16;                // b-frags per warp
    constexpr int CST = NT + 4;                  // C staging stride (floats)

    extern __shared__ __half sm[];

    const __half* Ag; const __half* Bg;
    if constexpr (MODE == 1) { Ag = g_x16;   Bg = g_mn16; }
    else if constexpr (MODE == 2) { Ag = g_score; Bg = g_wnT; }
    else if constexpr (MODE == 3) { Ag = g_h1;    Bg = g_w1T; }
    else { Ag = g_h2; Bg = g_w2T; }

    int tid = threadIdx.x, w = tid >> 5;
    int wm = w >> 1, wn = w & 1;                 // warp grid 2(M) x 2(N)
    int r0 = blockIdx.x * 128;
    int n0 = N0OFF + blockIdx.y * NT;

    auto load_stage = [&](int c, int s) {
        uint32_t abase = smem_u32(sm + s * STG);
        uint32_t bbase = abase + ASZ * 2;
        const __half* Ac = Ag + (size_t)r0 * K + c * 64;
        const __half* Bc = Bg + (size_t)n0 * K + c * 64;
#pragma unroll
        for (int v = tid; v < 128 * 8; v += 128) {
            int row = v >> 3, kv = v & 7;
            CP_ASYNC16(abase + (row * SA + kv * 8) * 2,
                       Ac + (size_t)row * K + kv * 8);
        }
#pragma unroll
        for (int v = tid; v < NT * 8; v += 128) {
            int row = v >> 3, kv = v & 7;
            CP_ASYNC16(bbase + (row * SA + kv * 8) * 2,
                       Bc + (size_t)row * K + kv * 8);
        }
    };

    wmma::fragment<wmma::accumulator, 16, 16, 16, float> acc[4][NF];
#pragma unroll
    for (int m = 0; m < 4; m++)
#pragma unroll
        for (int n = 0; n < NF; n++) wmma::fill_fragment(acc[m][n], 0.0f);

    load_stage(0, 0); CP_COMMIT;
    if (NIT > 1) { load_stage(1, 1); CP_COMMIT; }

    int stg = 0;                                 // = it % 3
    for (int it = 0; it < NIT; it++) {
        if (it == NIT - 1) { CP_WAIT0; } else { CP_WAIT1; }
        __syncthreads();   // publish all threads' copies; WAR-protect prefetch
        if (it + 2 < NIT) {
            int ps = stg + 2 >= 3 ? stg - 1 : stg + 2;   // (it+2)%3
            load_stage(it + 2, ps); CP_COMMIT;
        }
        const __half* As_ = sm + stg * STG;
        const __half* Bs_ = As_ + ASZ;
#pragma unroll
        for (int kk = 0; kk < 4; kk++) {
            wmma::fragment<wmma::matrix_a, 16, 16, 16, __half, wmma::row_major> af[4];
#pragma unroll
            for (int m = 0; m < 4; m++)
                wmma::load_matrix_sync(af[m], As_ + (wm * 64 + m * 16) * SA + kk * 16, SA);
#pragma unroll
            for (int n = 0; n < NF; n++) {
                wmma::fragment<wmma::matrix_b, 16, 16, 16, __half, wmma::col_major> bf;
                wmma::load_matrix_sync(bf, Bs_ + (wn * WNT + n * 16) * SA + kk * 16, SA);
#pragma unroll
                for (int m = 0; m < 4; m++)
                    wmma::mma_sync(acc[m][n], af[m], bf, acc[m][n]);
            }
        }
        if (++stg == 3) stg = 0;
    }
    __syncthreads();   // all compute done before Cs overwrites pipeline smem

    // ---- epilogue: stage C in smem (reuses pipeline smem) ----
    float* Cs = (float*)sm;
#pragma unroll
    for (int m = 0; m < 4; m++)
#pragma unroll
        for (int n = 0; n < NF; n++) {
            int lr = wm * 64 + m * 16, lc = wn * WNT + n * 16;
            if constexpr (MODE == 4)
                wmma::store_matrix_sync(Cs + lc * CST + lr, acc[m][n], CST,
                                        wmma::mem_col_major);
            else
                wmma::store_matrix_sync(Cs + lr * CST + lc, acc[m][n], CST,
                                        wmma::mem_row_major);
        }
    __syncthreads();

    if constexpr (MODE == 4) {
        // Cs[col][row]; thread -> 8 consecutive rows of one col: coalesced NCHW
        int cb = tid >> 4;                 // 0..7
        int rf = (tid & 15) * 8;
        int b = r0 >> 12, s0 = r0 & 4095;
#pragma unroll
        for (int pass = 0; pass < 16; pass++) {
            int c = cb + pass * 8, gc = n0 + c;
            float bv = bias[gc];
            float* op = out4 + (size_t)(b * 256 + gc) * 4096 + s0 + rf;
#pragma unroll
            for (int i = 0; i < 8; i++) op[i] = Cs[c * CST + rf + i] + bv;
        }
    } else {
        constexpr int CPR = NT / 8;        // 8-wide chunks per row
        for (int i = tid; i < 128 * CPR; i += 128) {
            int row = i / CPR, cg = (i % CPR) * 8;
            int gr = r0 + row;
            float scale = 1.0f;
            if constexpr (MODE == 1)
                scale = 1.0f / fmaxf(sqrtf(g_norm2[gr]), 1e-12f);
            __align__(16) __half hh[8];
#pragma unroll
            for (int q = 0; q < 8; q++) {
                float v = Cs[row * CST + cg + q];
                if constexpr (MODE == 1) v *= scale;
                if constexpr (MODE == 3) v = gelu_tanh(v + bias[n0 + cg + q]);
                hh[q] = __float2half(v);
            }
            __half* op;
            if constexpr (MODE == 1) op = g_score + (size_t)gr * 2048 + n0 + cg;
            else if constexpr (MODE == 2) op = g_h1 + (size_t)gr * H1W + n0 + cg;
            else op = g_h2 + (size_t)gr * 256 + n0 + cg;
            *(uint4*)op = *(uint4*)hh;
        }
    }
}

// ---------------------------------------------------------------------------
// row kernel: argmax (first-index ties) + softmax p (in place) + scatter.
// Warp-shfl reductions, 4 barriers total. One CTA (256 thr) per row.
__global__ __launch_bounds__(256) void rowproc_kernel(const float* __restrict__ y) {
    __shared__ float swv[8]; __shared__ int swi[8]; __shared__ float swsum[8];
    __shared__ float s_max; __shared__ int s_ind; __shared__ float s_inv;
    int r = blockIdx.x, t = threadIdx.x, w = t >> 5, lane = t & 31;
    __half* sp = g_score + (size_t)r * K_CODES;

    __align__(16) __half h[8];
    *(uint4*)h = ((const uint4*)sp)[t];
    float f[8];
    float mx = -1e30f; int mi = 0;
#pragma unroll
    for (int i = 0; i < 8; i++) {
        f[i] = __half2float(h[i]);
        if (f[i] > mx) { mx = f[i]; mi = t * 8 + i; }
    }
#pragma unroll
    for (int o = 16; o; o >>= 1) {
        float ov = __shfl_xor_sync(0xffffffffu, mx, o);
        int   oi = __shfl_xor_sync(0xffffffffu, mi, o);
        if (ov > mx || (ov == mx && oi < mi)) { mx = ov; mi = oi; }
    }
    if (lane == 0) { swv[w] = mx; swi[w] = mi; }
    __syncthreads();
    if (w == 0) {
        float v = (lane < 8) ? swv[lane] : -1e30f;
        int idx  = (lane < 8) ? swi[lane] : 0;
#pragma unroll
        for (int o = 4; o; o >>= 1) {
            float ov = __shfl_xor_sync(0xffffffffu, v, o);
            int   oi = __shfl_xor_sync(0xffffffffu, idx, o);
            if (ov > v || (ov == v && oi < idx)) { v = ov; idx = oi; }
        }
        if (lane == 0) { s_max = v; s_ind = idx; }
    }
    __syncthreads();
    float rowmax = s_max; int ind = s_ind;

    float e[8], sum = 0.f;
#pragma unroll
    for (int i = 0; i < 8; i++) { e[i] = __expf(f[i] - rowmax); sum += e[i]; }
#pragma unroll
    for (int o = 16; o; o >>= 1) sum += __shfl_xor_sync(0xffffffffu, sum, o);
    if (lane == 0) swsum[w] = sum;
    __syncthreads();
    if (w == 0) {
        float v = (lane < 8) ? swsum[lane] : 0.f;
#pragma unroll
        for (int o = 4; o; o >>= 1) v += __shfl_xor_sync(0xffffffffu, v, o);
        if (lane == 0) s_inv = 1.0f / v;
    }
    __syncthreads();
    float inv = s_inv;
    __align__(16) __half o8[8];
#pragma unroll
    for (int i = 0; i < 8; i++) o8[i] = __float2half(e[i] * inv);
    ((uint4*)sp)[t] = *(uint4*)o8;

    float xv = __half2float(g_x16[(size_t)r * C_DIM + t]);
    atomicAdd(&g_sums[ind * CD + t], xv);
    if (t < 4) {
        int b = r >> 12, sidx = r & 4095;
        atomicAdd(&g_sums[ind * CD + 256 + t], y[((b * 4 + t) << 12) + sidx]);
    }
    if (t == 0) atomicAdd(&g_counts[ind], 1.0f);
}

// EMA update + l2norm over 260 -> g_wn fp16 (row-major, zero-padded). CTA/row.
__global__ __launch_bounds__(256) void neww_kernel(const float* __restrict__ fw) {
    __shared__ float red[256];
    int k = blockIdx.x, t = threadIdx.x;
    float denom = 1.0f / (g_counts[k] + 1e-6f);
    float v0, v1 = 0.f;
    {
        float a = fw[(size_t)k * CD + t];
        float sm2 = g_sums[k * CD + t];
        v0 = a * 0.999f + 0.001f * sm2 * denom;
    }
    if (t < 4) {
        int j = 256 + t;
        float a = fw[(size_t)k * CD + j];
        float sm2 = g_sums[k * CD + j];
        v1 = a * 0.999f + 0.001f * sm2 * denom;
    }
    red[t] = v0 * v0 + v1 * v1;
    __syncthreads();
    for (int o = 128; o; o >>= 1) {
        if (t < o) red[t] += red[t + o];
        __syncthreads();
    }
    float ri = 1.0f / fmaxf(sqrtf(red[0]), 1e-12f);
    g_wn[k * H1W + t] = __float2half(v0 * ri);
    if (t < 4)  g_wn[k * H1W + 256 + t] = __float2half(v1 * ri);
    if (t < 60) g_wn[k * H1W + 260 + t] = __float2half(0.f);
}

// transpose g_wn [2048][320] -> g_wnT [320][2048]. grid (64,10), block (32,8)
__global__ void wnT_kernel() {
    __shared__ __half tile[32][33];
    int k0 = blockIdx.x * 32, j0 = blockIdx.y * 32;
    int tx = threadIdx.x, ty = threadIdx.y;
#pragma unroll
    for (int jj = 0; jj < 32; jj += 8)
        tile[ty + jj][tx] = g_wn[(k0 + ty + jj) * H1W + j0 + tx];
    __syncthreads();
#pragma unroll
    for (int jj = 0; jj < 32; jj += 8)
        g_wnT[(size_t)(j0 + ty + jj) * K_CODES + k0 + tx] = tile[tx][ty + jj];
}

// ---------------------------------------------------------------------------
extern "C" void kernel_launch(void* const* d_in, const int* in_sizes, int n_in,
                              void* d_out, int out_size) {
    const float* x  = (const float*)d_in[0];
    const float* y  = (const float*)d_in[1];
    const float* fw = (const float*)d_in[2];
    const float* w1 = (const float*)d_in[3];
    const float* b1 = (const float*)d_in[4];
    const float* w2 = (const float*)d_in[5];
    const float* b2 = (const float*)d_in[6];
    float* out = (float*)d_out;

    constexpr int SM3_128 = 3 * (128 + 128) * 72 * 2;   // 110592 (>= Cs 67584)
    constexpr int SM3_64  = 3 * (128 + 64) * 72 * 2;    // 82944  (>= Cs 34816)
    cudaFuncSetAttribute(st_gemm<1,128,0>,   cudaFuncAttributeMaxDynamicSharedMemorySize, SM3_128);
    cudaFuncSetAttribute(st_gemm<2,128,0>,   cudaFuncAttributeMaxDynamicSharedMemorySize, SM3_128);
    cudaFuncSetAttribute(st_gemm<2,64,256>,  cudaFuncAttributeMaxDynamicSharedMemorySize, SM3_64);
    cudaFuncSetAttribute(st_gemm<3,128,0>,   cudaFuncAttributeMaxDynamicSharedMemorySize, SM3_128);
    cudaFuncSetAttribute(st_gemm<4,128,0>,   cudaFuncAttributeMaxDynamicSharedMemorySize, SM3_128);

    prep_misc_kernel<<<512, 256>>>(w1, w2);
    prep_x_kernel<<<dim3(128, 8, 8), dim3(32, 8)>>>(x);
    prep_mn_kernel<<<256, 256>>>(fw);

    st_gemm<1,128,0><<<dim3(256, 16), 128, SM3_128>>>(nullptr, nullptr); // score
    rowproc_kernel<<<32768, 256>>>(y);                                   // softmax+scatter
    neww_kernel<<<2048, 256>>>(fw);                                      // EMA + norm
    wnT_kernel<<<dim3(64, 10), dim3(32, 8)>>>();                         // transpose wn
    st_gemm<2,128,0><<<dim3(256, 2), 128, SM3_128>>>(nullptr, nullptr);  // p@wn [0:256)
    st_gemm<2,64,256><<<dim3(256, 1), 128, SM3_64>>>(nullptr, nullptr);  // p@wn [256:320)
    st_gemm<3,128,0><<<dim3(256, 2), 128, SM3_128>>>(b1, nullptr);       // MLP layer 1
    st_gemm<4,128,0><<<dim3(256, 2), 128, SM3_128>>>(b2, out);           // MLP layer 2
}

// round 17
// speedup vs baseline: 1.0746x; 1.0746x over previous
#include <cuda_runtime.h>
#include <cuda_fp16.h>
#include <mma.h>
#include <cstdint>

using namespace nvcuda;

// ---------------------------------------------------------------------------
#define N_ROWS 32768     // b*h*w = 8*64*64
#define C_DIM  256
#define K_CODES 2048
#define CD     260       // c+4
#define H1W    320       // padded hidden1 / wn width

// Scratch (device globals -- allocation is forbidden).
// NOTE: device globals are zero-initialized; g_h1 cols [288,320) are never
// written and stay 0, and g_wn pads cols [260,320) with zeros each call, so
// computing h1 only on [0,288) is exact.
__device__ __half  g_x16[N_ROWS * C_DIM];                 // fp16 x_flat (n,256)
__device__ float   g_norm2[N_ROWS];                       // sum x^2 per row (fp32)
__device__ __half  g_mn16[K_CODES * C_DIM];               // normalized codebook fp16
__device__ __half  g_score[(size_t)N_ROWS * K_CODES];     // score, then p (in place)
__device__ float   g_sums[K_CODES * CD];
__device__ float   g_counts[K_CODES];
__device__ __half  g_wn[K_CODES * H1W];                   // l2norm(new_w) row-major
__device__ __half  g_wnT[H1W * K_CODES];                  // transposed [320][2048]
__device__ __half  g_h1[(size_t)N_ROWS * H1W];            // p @ wn  (n,320)
__device__ __half  g_h2[(size_t)N_ROWS * C_DIM];          // gelu(h1@w1+b1)
__device__ __half  g_w1T[C_DIM * H1W];                    // w1^T fp16 [256][320] pad
__device__ __half  g_w2T[C_DIM * C_DIM];                  // w2^T fp16

// ---------------------------------------------------------------------------
#define CP_ASYNC16(dst, src) \
    asm volatile("cp.async.cg.shared.global [%0], [%1], 16;\n" \
                 :: "r"(dst), "l"(src) : "memory")
#define CP_COMMIT asm volatile("cp.async.commit_group;\n" ::: "memory")
#define CP_WAIT1  asm volatile("cp.async.wait_group 1;\n" ::: "memory")
#define CP_WAIT0  asm volatile("cp.async.wait_group 0;\n" ::: "memory")

__device__ __forceinline__ uint32_t smem_u32(const void* p) {
    uint32_t a;
    asm("{ .reg .u64 t; cvta.to.shared.u64 t, %1; cvt.u32.u64 %0, t; }"
        : "=r"(a) : "l"(p));
    return a;
}

__device__ __forceinline__ float gelu_tanh(float v) {
    float u = 0.7978845608028654f * (v + 0.044715f * v * v * v);
    return 0.5f * v * (1.0f + tanhf(u));
}

// ---------------------------------------------------------------------------
// prep: zero sums/counts/norm2, build transposed fp16 weights
__global__ void prep_misc_kernel(const float* __restrict__ w1,
                                 const float* __restrict__ w2) {
    int t = blockIdx.x * blockDim.x + threadIdx.x;
    int nthr = gridDim.x * blockDim.x;
    for (int i = t; i < K_CODES * CD; i += nthr) g_sums[i] = 0.f;
    for (int i = t; i < K_CODES; i += nthr) g_counts[i] = 0.f;
    for (int i = t; i < N_ROWS; i += nthr) g_norm2[i] = 0.f;
    for (int i = t; i < C_DIM * H1W; i += nthr) {
        int j = i / H1W, k = i % H1W;
        g_w1T[i] = __float2half(k < CD ? w1[k * C_DIM + j] : 0.f);
    }
    for (int i = t; i < C_DIM * C_DIM; i += nthr) {
        int j = i >> 8, k = i & 255;
        g_w2T[i] = __float2half(w2[k * C_DIM + j]);
    }
}

// NCHW -> (n,256) fp16 transpose + partial row-norm2 atomics.
// grid (128, 8, 8), block (32, 8)
__global__ void prep_x_kernel(const float* __restrict__ x) {
    __shared__ float tile[32][33];
    int b = blockIdx.z, c0 = blockIdx.y * 32, s0 = blockIdx.x * 32;
    int tx = threadIdx.x, ty = threadIdx.y;
#pragma unroll
    for (int j = 0; j < 32; j += 8)
        tile[ty + j][tx] = x[(size_t)(b * 256 + c0 + ty + j) * 4096 + s0 + tx];
    __syncthreads();
#pragma unroll
    for (int j = 0; j < 32; j += 8) {
        int c = c0 + tx, s = s0 + ty + j, r = (b << 12) + s;
        float v = tile[tx][ty + j];
        g_x16[r * C_DIM + c] = __float2half(v);
        float sq = v * v;
#pragma unroll
        for (int o = 16; o; o >>= 1) sq += __shfl_xor_sync(0xffffffffu, sq, o);
        if (tx == 0) atomicAdd(&g_norm2[r], sq);
    }
}

// normalize codebook feature rows -> g_mn16. warp per row.
__global__ void prep_mn_kernel(const float* __restrict__ fw) {
    int wid = threadIdx.x >> 5, lane = threadIdx.x & 31;
    int k = blockIdx.x * 8 + wid;
    if (k >= K_CODES) return;
    const float* p = fw + (size_t)k * CD;
    float v[8], s = 0.f;
#pragma unroll
    for (int j = 0; j < 8; j++) { v[j] = p[lane + j * 32]; s += v[j] * v[j]; }
#pragma unroll
    for (int o = 16; o; o >>= 1) s += __shfl_xor_sync(0xffffffffu, s, o);
    float ri = 1.0f / fmaxf(sqrtf(s), 1e-12f);
#pragma unroll
    for (int j = 0; j < 8; j++)
        g_mn16[k * C_DIM + lane + j * 32] = __float2half(v[j] * ri);
}

// ---------------------------------------------------------------------------
// Streaming HMMA GEMM: CTA tile 128 x NT, 256 threads, 8 warps (4x2),
// warp tile 32 x NT/2. cp.async ring: TS3 ? 3-stage/1-barrier : 2-stage/
// 2-barrier (both schedules race-free and bench-proven). 2 CTAs/SM.
// MODE 1: score = x16 @ mn^T  (*rinv)   -> g_score fp16
// MODE 2: h1    = p @ wnT^T             -> g_h1 fp16  (N covered [0,288) only)
// MODE 3: h2    = gelu(h1 @ w1T^T + b1) -> g_h2 fp16
// MODE 4: out   = h2 @ w2T^T + b2       -> NCHW fp32
template <int MODE, int NT, int N0OFF, int KDIM, bool TS3>
__global__ __launch_bounds__(256, 2) void st_gemm(const float* __restrict__ bias,
                                                  float* __restrict__ out4) {
    constexpr int K  = KDIM;                     // loop K == stride (row-major)
    constexpr int NIT = K / 64;
    constexpr int SA = 72;                       // smem k-stride (halves)
    constexpr int ASZ = 128 * SA;                // halves per A stage
    constexpr int BSZ = NT * SA;
    constexpr int STG = ASZ + BSZ;
    constexpr int WNT = NT / 2;                  // per-warp N (warps 4x2)
    constexpr int NF  = WNT / 16;                // b-frags per warp
    constexpr int CST = NT + 4;                  // C staging stride (floats)

    extern __shared__ __half sm[];

    const __half* Ag; const __half* Bg;
    if constexpr (MODE == 1) { Ag = g_x16;   Bg = g_mn16; }
    else if constexpr (MODE == 2) { Ag = g_score; Bg = g_wnT; }
    else if constexpr (MODE == 3) { Ag = g_h1;    Bg = g_w1T; }
    else { Ag = g_h2; Bg = g_w2T; }

    int tid = threadIdx.x, w = tid >> 5;
    int wm = w & 3, wn = w >> 2;                 // warp grid 4(M) x 2(N)
    int r0 = blockIdx.x * 128;
    int n0 = N0OFF + blockIdx.y * NT;

    auto load_stage = [&](int c, int s) {
        uint32_t abase = smem_u32(sm + s * STG);
        uint32_t bbase = abase + ASZ * 2;
        const __half* Ac = Ag + (size_t)r0 * K + c * 64;
        const __half* Bc = Bg + (size_t)n0 * K + c * 64;
#pragma unroll
        for (int v = tid; v < 128 * 8; v += 256) {
            int row = v >> 3, kv = v & 7;
            CP_ASYNC16(abase + (row * SA + kv * 8) * 2,
                       Ac + (size_t)row * K + kv * 8);
        }
#pragma unroll
        for (int v = tid; v < NT * 8; v += 256) {
            int row = v >> 3, kv = v & 7;
            CP_ASYNC16(bbase + (row * SA + kv * 8) * 2,
                       Bc + (size_t)row * K + kv * 8);
        }
    };

    wmma::fragment<wmma::accumulator, 16, 16, 16, float> acc[2][NF];
#pragma unroll
    for (int m = 0; m < 2; m++)
#pragma unroll
        for (int n = 0; n < NF; n++) wmma::fill_fragment(acc[m][n], 0.0f);

    auto compute_stage = [&](const __half* As_, const __half* Bs_) {
#pragma unroll
        for (int kk = 0; kk < 4; kk++) {
            wmma::fragment<wmma::matrix_a, 16, 16, 16, __half, wmma::row_major> af[2];
#pragma unroll
            for (int m = 0; m < 2; m++)
                wmma::load_matrix_sync(af[m], As_ + (wm * 32 + m * 16) * SA + kk * 16, SA);
#pragma unroll
            for (int n = 0; n < NF; n++) {
                wmma::fragment<wmma::matrix_b, 16, 16, 16, __half, wmma::col_major> bf;
                wmma::load_matrix_sync(bf, Bs_ + (wn * WNT + n * 16) * SA + kk * 16, SA);
#pragma unroll
                for (int m = 0; m < 2; m++)
                    wmma::mma_sync(acc[m][n], af[m], bf, acc[m][n]);
            }
        }
    };

    if constexpr (TS3) {
        // 3-stage ring, prefetch distance 2, one barrier per iter (after the
        // wait: publishes all threads' copies of the compute stage and proves
        // compute of it-1 finished before its stage is overwritten).
        load_stage(0, 0); CP_COMMIT;
        load_stage(1, 1); CP_COMMIT;
        int stg = 0;
        for (int it = 0; it < NIT; it++) {
            if (it == NIT - 1) { CP_WAIT0; } else { CP_WAIT1; }
            __syncthreads();
            if (it + 2 < NIT) {
                int ps = stg + 2 >= 3 ? stg - 1 : stg + 2;   // (it+2)%3
                load_stage(it + 2, ps); CP_COMMIT;
            }
            const __half* As_ = sm + stg * STG;
            compute_stage(As_, As_ + ASZ);
            if (++stg == 3) stg = 0;
        }
        __syncthreads();
    } else {
        // 2-stage ring, two barriers per iter (R11-proven).
        load_stage(0, 0); CP_COMMIT;
        for (int it = 0; it < NIT; it++) {
            int s = it & 1;
            if (it + 1 < NIT) { load_stage(it + 1, s ^ 1); CP_COMMIT; CP_WAIT1; }
            else              { CP_WAIT0; }
            __syncthreads();
            const __half* As_ = sm + s * STG;
            compute_stage(As_, As_ + ASZ);
            __syncthreads();
        }
    }

    // ---- epilogue: stage C in smem (reuses pipeline smem) ----
    float* Cs = (float*)sm;
#pragma unroll
    for (int m = 0; m < 2; m++)
#pragma unroll
        for (int n = 0; n < NF; n++) {
            int lr = wm * 32 + m * 16, lc = wn * WNT + n * 16;
            if constexpr (MODE == 4)
                wmma::store_matrix_sync(Cs + lc * CST + lr, acc[m][n], CST,
                                        wmma::mem_col_major);
            else
                wmma::store_matrix_sync(Cs + lr * CST + lc, acc[m][n], CST,
                                        wmma::mem_row_major);
        }
    __syncthreads();

    if constexpr (MODE == 4) {
        // Cs[col][row]; thread -> 8 consecutive rows of one col: coalesced NCHW
        int cb = tid >> 4;                 // 0..15
        int rf = (tid & 15) * 8;
        int b = r0 >> 12, s0 = r0 & 4095;
#pragma unroll
        for (int pass = 0; pass < 8; pass++) {
            int c = cb + pass * 16, gc = n0 + c;
            float bv = bias[gc];
            float* op = out4 + (size_t)(b * 256 + gc) * 4096 + s0 + rf;
#pragma unroll
            for (int i = 0; i < 8; i++) op[i] = Cs[c * CST + rf + i] + bv;
        }
    } else {
        constexpr int CPR = NT / 8;        // 8-wide chunks per row
        for (int i = tid; i < 128 * CPR; i += 256) {
            int row = i / CPR, cg = (i % CPR) * 8;
            int gr = r0 + row;
            float scale = 1.0f;
            if constexpr (MODE == 1)
                scale = 1.0f / fmaxf(sqrtf(g_norm2[gr]), 1e-12f);
            __align__(16) __half hh[8];
#pragma unroll
            for (int q = 0; q < 8; q++) {
                float v = Cs[row * CST + cg + q];
                if constexpr (MODE == 1) v *= scale;
                if constexpr (MODE == 3) v = gelu_tanh(v + bias[n0 + cg + q]);
                hh[q] = __float2half(v);
            }
            __half* op;
            if constexpr (MODE == 1) op = g_score + (size_t)gr * 2048 + n0 + cg;
            else if constexpr (MODE == 2) op = g_h1 + (size_t)gr * H1W + n0 + cg;
            else op = g_h2 + (size_t)gr * 256 + n0 + cg;
            *(uint4*)op = *(uint4*)hh;
        }
    }
}

// ---------------------------------------------------------------------------
// row kernel: argmax (first-index ties) + softmax p (in place) + scatter.
// Warp-shfl reductions, 4 barriers total. One CTA (256 thr) per row.
__global__ __launch_bounds__(256) void rowproc_kernel(const float* __restrict__ y) {
    __shared__ float swv[8]; __shared__ int swi[8]; __shared__ float swsum[8];
    __shared__ float s_max; __shared__ int s_ind; __shared__ float s_inv;
    int r = blockIdx.x, t = threadIdx.x, w = t >> 5, lane = t & 31;
    __half* sp = g_score + (size_t)r * K_CODES;

    __align__(16) __half h[8];
    *(uint4*)h = ((const uint4*)sp)[t];
    float f[8];
    float mx = -1e30f; int mi = 0;
#pragma unroll
    for (int i = 0; i < 8; i++) {
        f[i] = __half2float(h[i]);
        if (f[i] > mx) { mx = f[i]; mi = t * 8 + i; }
    }
#pragma unroll
    for (int o = 16; o; o >>= 1) {
        float ov = __shfl_xor_sync(0xffffffffu, mx, o);
        int   oi = __shfl_xor_sync(0xffffffffu, mi, o);
        if (ov > mx || (ov == mx && oi < mi)) { mx = ov; mi = oi; }
    }
    if (lane == 0) { swv[w] = mx; swi[w] = mi; }
    __syncthreads();
    if (w == 0) {
        float v = (lane < 8) ? swv[lane] : -1e30f;
        int idx  = (lane < 8) ? swi[lane] : 0;
#pragma unroll
        for (int o = 4; o; o >>= 1) {
            float ov = __shfl_xor_sync(0xffffffffu, v, o);
            int   oi = __shfl_xor_sync(0xffffffffu, idx, o);
            if (ov > v || (ov == v && oi < idx)) { v = ov; idx = oi; }
        }
        if (lane == 0) { s_max = v; s_ind = idx; }
    }
    __syncthreads();
    float rowmax = s_max; int ind = s_ind;

    float e[8], sum = 0.f;
#pragma unroll
    for (int i = 0; i < 8; i++) { e[i] = __expf(f[i] - rowmax); sum += e[i]; }
#pragma unroll
    for (int o = 16; o; o >>= 1) sum += __shfl_xor_sync(0xffffffffu, sum, o);
    if (lane == 0) swsum[w] = sum;
    __syncthreads();
    if (w == 0) {
        float v = (lane < 8) ? swsum[lane] : 0.f;
#pragma unroll
        for (int o = 4; o; o >>= 1) v += __shfl_xor_sync(0xffffffffu, v, o);
        if (lane == 0) s_inv = 1.0f / v;
    }
    __syncthreads();
    float inv = s_inv;
    __align__(16) __half o8[8];
#pragma unroll
    for (int i = 0; i < 8; i++) o8[i] = __float2half(e[i] * inv);
    ((uint4*)sp)[t] = *(uint4*)o8;

    float xv = __half2float(g_x16[(size_t)r * C_DIM + t]);
    atomicAdd(&g_sums[ind * CD + t], xv);
    if (t < 4) {
        int b = r >> 12, sidx = r & 4095;
        atomicAdd(&g_sums[ind * CD + 256 + t], y[((b * 4 + t) << 12) + sidx]);
    }
    if (t == 0) atomicAdd(&g_counts[ind], 1.0f);
}

// EMA update + l2norm over 260 -> g_wn fp16 (row-major, zero-padded). CTA/row.
__global__ __launch_bounds__(256) void neww_kernel(const float* __restrict__ fw) {
    __shared__ float red[256];
    int k = blockIdx.x, t = threadIdx.x;
    float denom = 1.0f / (g_counts[k] + 1e-6f);
    float v0, v1 = 0.f;
    {
        float a = fw[(size_t)k * CD + t];
        float sm2 = g_sums[k * CD + t];
        v0 = a * 0.999f + 0.001f * sm2 * denom;
    }
    if (t < 4) {
        int j = 256 + t;
        float a = fw[(size_t)k * CD + j];
        float sm2 = g_sums[k * CD + j];
        v1 = a * 0.999f + 0.001f * sm2 * denom;
    }
    red[t] = v0 * v0 + v1 * v1;
    __syncthreads();
    for (int o = 128; o; o >>= 1) {
        if (t < o) red[t] += red[t + o];
        __syncthreads();
    }
    float ri = 1.0f / fmaxf(sqrtf(red[0]), 1e-12f);
    g_wn[k * H1W + t] = __float2half(v0 * ri);
    if (t < 4)  g_wn[k * H1W + 256 + t] = __float2half(v1 * ri);
    if (t < 60) g_wn[k * H1W + 260 + t] = __float2half(0.f);
}

// transpose g_wn [2048][320] -> g_wnT [320][2048]. grid (64,10), block (32,8)
__global__ void wnT_kernel() {
    __shared__ __half tile[32][33];
    int k0 = blockIdx.x * 32, j0 = blockIdx.y * 32;
    int tx = threadIdx.x, ty = threadIdx.y;
#pragma unroll
    for (int jj = 0; jj < 32; jj += 8)
        tile[ty + jj][tx] = g_wn[(k0 + ty + jj) * H1W + j0 + tx];
    __syncthreads();
#pragma unroll
    for (int jj = 0; jj < 32; jj += 8)
        g_wnT[(size_t)(j0 + ty + jj) * K_CODES + k0 + tx] = tile[tx][ty + jj];
}

// ---------------------------------------------------------------------------
extern "C" void kernel_launch(void* const* d_in, const int* in_sizes, int n_in,
                              void* d_out, int out_size) {
    const float* x  = (const float*)d_in[0];
    const float* y  = (const float*)d_in[1];
    const float* fw = (const float*)d_in[2];
    const float* w1 = (const float*)d_in[3];
    const float* b1 = (const float*)d_in[4];
    const float* w2 = (const float*)d_in[5];
    const float* b2 = (const float*)d_in[6];
    float* out = (float*)d_out;

    constexpr int SM3_128 = 3 * (128 + 128) * 72 * 2;   // 110592 (>= Cs 67584)
    constexpr int SM2_160 = 128 * 164 * 4;              // 83968  (>= 2 stages 82944)
    cudaFuncSetAttribute((const void*)st_gemm<1,128,0,256,true>,
                         cudaFuncAttributeMaxDynamicSharedMemorySize, SM3_128);
    cudaFuncSetAttribute((const void*)st_gemm<2,160,0,2048,false>,
                         cudaFuncAttributeMaxDynamicSharedMemorySize, SM2_160);
    cudaFuncSetAttribute((const void*)st_gemm<2,128,160,2048,true>,
                         cudaFuncAttributeMaxDynamicSharedMemorySize, SM3_128);
    cudaFuncSetAttribute((const void*)st_gemm<3,128,0,320,true>,
                         cudaFuncAttributeMaxDynamicSharedMemorySize, SM3_128);
    cudaFuncSetAttribute((const void*)st_gemm<4,128,0,256,true>,
                         cudaFuncAttributeMaxDynamicSharedMemorySize, SM3_128);

    prep_misc_kernel<<<512, 256>>>(w1, w2);
    prep_x_kernel<<<dim3(128, 8, 8), dim3(32, 8)>>>(x);
    prep_mn_kernel<<<256, 256>>>(fw);

    st_gemm<1,128,0,256,true><<<dim3(256, 16), 256, SM3_128>>>(nullptr, nullptr);
    rowproc_kernel<<<32768, 256>>>(y);                                // softmax+scatter
    neww_kernel<<<2048, 256>>>(fw);                                   // EMA + norm
    wnT_kernel<<<dim3(64, 10), dim3(32, 8)>>>();                      // transpose wn
    st_gemm<2,160,0,2048,false><<<dim3(256, 1), 256, SM2_160>>>(nullptr, nullptr); // p@wn [0,160)
    st_gemm<2,128,160,2048,true><<<dim3(256, 1), 256, SM3_128>>>(nullptr, nullptr);// p@wn [160,288)
    st_gemm<3,128,0,320,true><<<dim3(256, 2), 256, SM3_128>>>(b1, nullptr);        // MLP layer 1
    st_gemm<4,128,0,256,true><<<dim3(256, 2), 256, SM3_128>>>(b2, out);            // MLP layer 2
}